// round 6
// baseline (speedup 1.0000x reference)
#include <cuda_runtime.h>
#include <cuda_bf16.h>
#include <math.h>
#include <stdint.h>

// ---------------- problem constants ----------------
#define MAXN   50000
#define DIM    96
#define KNBR   16
#define NBIAS  15
#define SCALE  0.25f
#define TBL_ROWS 64

typedef unsigned long long ull;

// ---------------- device scratch ----------------
__device__ __align__(16) float g_q[MAXN * DIM];
__device__ __align__(16) float g_k[MAXN * DIM];
__device__ __align__(16) float g_v[MAXN * DIM];
__device__ __align__(16) float g_x[MAXN * DIM];
// tq/tk interleaved bf16: [c][row][24 groups][tq0..3, tk0..3]
__device__ __align__(16) __nv_bfloat16 g_tqk[3 * TBL_ROWS * 192];
// tv fp32 c-major: [c][row][96]
__device__ __align__(16) float g_tv[3 * TBL_ROWS * DIM];
// W_qkv paired: u64[dp][288]  (w[2dp][c], w[2dp+1][c])
__device__ __align__(16) float g_wq[48 * 576];
// W_proj paired: u64[dp][96]
__device__ __align__(16) float g_wp[48 * 192];
__device__ int g_quant[MAXN];
__device__ unsigned int g_minbits[3];

// ---------------- f32x2 helpers ----------------
__device__ __forceinline__ ull fma2(ull a, ull b, ull c) {
    ull d;
    asm("fma.rn.f32x2 %0, %1, %2, %3;" : "=l"(d) : "l"(a), "l"(b), "l"(c));
    return d;
}
__device__ __forceinline__ float f2sum(ull a) {
    unsigned lo, hi;
    asm("mov.b64 {%0, %1}, %2;" : "=r"(lo), "=r"(hi) : "l"(a));
    return __uint_as_float(lo) + __uint_as_float(hi);
}
__device__ __forceinline__ float2 bf2f(unsigned u) {
    __nv_bfloat162 h = *reinterpret_cast<__nv_bfloat162*>(&u);
    return __bfloat1622float2(h);
}

// ---------------- kernel 0: init min ----------------
__global__ void k_init_min() {
    if (threadIdx.x < 3) g_minbits[threadIdx.x] = 0x7F800000u;
}

// ---------------- kernel 1: xyz min ----------------
__global__ void k_min(const float* __restrict__ xyz, int N) {
    float v0 = INFINITY, v1 = INFINITY, v2 = INFINITY;
    for (int i = blockIdx.x * blockDim.x + threadIdx.x; i < N;
         i += gridDim.x * blockDim.x) {
        v0 = fminf(v0, xyz[i * 3 + 0]);
        v1 = fminf(v1, xyz[i * 3 + 1]);
        v2 = fminf(v2, xyz[i * 3 + 2]);
    }
    #pragma unroll
    for (int m = 16; m >= 1; m >>= 1) {
        v0 = fminf(v0, __shfl_xor_sync(0xFFFFFFFFu, v0, m));
        v1 = fminf(v1, __shfl_xor_sync(0xFFFFFFFFu, v1, m));
        v2 = fminf(v2, __shfl_xor_sync(0xFFFFFFFFu, v2, m));
    }
    if ((threadIdx.x & 31) == 0) {
        atomicMin(&g_minbits[0], __float_as_uint(v0));
        atomicMin(&g_minbits[1], __float_as_uint(v1));
        atomicMin(&g_minbits[2], __float_as_uint(v2));
    }
}

// ---------------- kernel 2: quant + table repack + W repack ----------------
__global__ void k_prep(const float* __restrict__ xyz,
                       const float* __restrict__ shift_ptr,
                       const float* __restrict__ tq,
                       const float* __restrict__ tk,
                       const float* __restrict__ tv,
                       const float* __restrict__ Wq,
                       const float* __restrict__ Wp, int N) {
    int i = blockIdx.x * blockDim.x + threadIdx.x;
    if (i < N) {
        float shift = shift_ptr ? *shift_ptr : 0.0f;
        int packed = 0;
        #pragma unroll
        for (int c = 0; c < 3; c++) {
            float mn = __uint_as_float(g_minbits[c]);
            float m = fmodf(xyz[i * 3 + c] - mn + shift, 4.0f);
            if (m < 0.0f) m += 4.0f;
            int q = (int)floorf(m * 4.0f);
            q = max(0, min(15, q));
            packed |= q << (8 * c);
        }
        g_quant[i] = packed;
    }
    if (i < 3 * TBL_ROWS * DIM) {
        int c = i / (TBL_ROWS * DIM);
        int rem = i % (TBL_ROWS * DIM);
        int r = rem / DIM, dim = rem % DIM;
        int src = (r * DIM + dim) * 3 + c;
        int gdst = (c * TBL_ROWS + r) * 192 + (dim / 4) * 8 + (dim % 4);
        g_tqk[gdst]     = __float2bfloat16(tq[src]);
        g_tqk[gdst + 4] = __float2bfloat16(tk[src]);
        g_tv[(c * TBL_ROWS + r) * DIM + dim] = tv[src];
    }
    if (i < 48 * 576) {
        int dp = i / 576, rem = i % 576;
        int c = rem >> 1, par = rem & 1;
        g_wq[i] = Wq[(2 * dp + par) * 288 + c];
    }
    if (i < 48 * 192) {
        int dp = i / 192, rem = i % 192;
        int c = rem >> 1, par = rem & 1;
        g_wp[i] = Wp[(2 * dp + par) * DIM + c];
    }
}

// ---------------- kernel 3: QKV GEMM, rows-on-lanes, uniform weights ----
// block 384 = 12 warps. warp w -> cols 8w..8w+7 (within the gridy 96-col tile).
// lane owns rows lane, lane+32 of a 64-row block. gridDim.y=3 picks q/k/v.
#define SF_STRIDE 98
#define SO_STRIDE 100
__global__ __launch_bounds__(384, 2) void k_qkv(const float* __restrict__ feats,
                                                const float* __restrict__ b, int N) {
    __shared__ __align__(16) float sf[64 * SF_STRIDE];
    __shared__ __align__(16) float so[64 * SO_STRIDE];
    int row0 = blockIdx.x * 64;
    int ct = blockIdx.y;
    int t = threadIdx.x;

    for (int idx = t; idx < 64 * 24; idx += 384) {
        int r = idx / 24, c4 = idx % 24;
        float4 v = (row0 + r < N)
            ? *reinterpret_cast<const float4*>(&feats[(row0 + r) * DIM + 4 * c4])
            : make_float4(0.f, 0.f, 0.f, 0.f);
        *reinterpret_cast<float2*>(&sf[r * SF_STRIDE + 4 * c4])     = make_float2(v.x, v.y);
        *reinterpret_cast<float2*>(&sf[r * SF_STRIDE + 4 * c4 + 2]) = make_float2(v.z, v.w);
    }
    __syncthreads();

    int wid = t >> 5, lane = t & 31;
    int colw = wid * 8;                    // 0..88 within tile
    int colg = ct * DIM + colw;            // global col

    ull acc0[8], acc1[8];
    #pragma unroll
    for (int c = 0; c < 8; c++) { acc0[c] = 0ull; acc1[c] = 0ull; }

    const ull* wbase = reinterpret_cast<const ull*>(g_wq) + colg;
    const float* s0p = &sf[lane * SF_STRIDE];
    const float* s1p = &sf[(lane + 32) * SF_STRIDE];

    #pragma unroll 4
    for (int dp = 0; dp < 48; dp++) {
        ulonglong2 wa = *reinterpret_cast<const ulonglong2*>(wbase + dp * 288);
        ulonglong2 wb = *reinterpret_cast<const ulonglong2*>(wbase + dp * 288 + 2);
        ulonglong2 wc = *reinterpret_cast<const ulonglong2*>(wbase + dp * 288 + 4);
        ulonglong2 wd = *reinterpret_cast<const ulonglong2*>(wbase + dp * 288 + 6);
        ull s0 = *reinterpret_cast<const ull*>(s0p + 2 * dp);
        ull s1 = *reinterpret_cast<const ull*>(s1p + 2 * dp);
        acc0[0] = fma2(s0, wa.x, acc0[0]);  acc1[0] = fma2(s1, wa.x, acc1[0]);
        acc0[1] = fma2(s0, wa.y, acc0[1]);  acc1[1] = fma2(s1, wa.y, acc1[1]);
        acc0[2] = fma2(s0, wb.x, acc0[2]);  acc1[2] = fma2(s1, wb.x, acc1[2]);
        acc0[3] = fma2(s0, wb.y, acc0[3]);  acc1[3] = fma2(s1, wb.y, acc1[3]);
        acc0[4] = fma2(s0, wc.x, acc0[4]);  acc1[4] = fma2(s1, wc.x, acc1[4]);
        acc0[5] = fma2(s0, wc.y, acc0[5]);  acc1[5] = fma2(s1, wc.y, acc1[5]);
        acc0[6] = fma2(s0, wd.x, acc0[6]);  acc1[6] = fma2(s1, wd.x, acc1[6]);
        acc0[7] = fma2(s0, wd.y, acc0[7]);  acc1[7] = fma2(s1, wd.y, acc1[7]);
    }

    float sc = (ct == 0) ? SCALE : 1.0f;
    float4 b0 = *reinterpret_cast<const float4*>(&b[colg]);
    float4 b1 = *reinterpret_cast<const float4*>(&b[colg + 4]);
    {
        float4 o;
        o.x = (f2sum(acc0[0]) + b0.x) * sc;
        o.y = (f2sum(acc0[1]) + b0.y) * sc;
        o.z = (f2sum(acc0[2]) + b0.z) * sc;
        o.w = (f2sum(acc0[3]) + b0.w) * sc;
        *reinterpret_cast<float4*>(&so[lane * SO_STRIDE + colw]) = o;
        o.x = (f2sum(acc0[4]) + b1.x) * sc;
        o.y = (f2sum(acc0[5]) + b1.y) * sc;
        o.z = (f2sum(acc0[6]) + b1.z) * sc;
        o.w = (f2sum(acc0[7]) + b1.w) * sc;
        *reinterpret_cast<float4*>(&so[lane * SO_STRIDE + colw + 4]) = o;
        o.x = (f2sum(acc1[0]) + b0.x) * sc;
        o.y = (f2sum(acc1[1]) + b0.y) * sc;
        o.z = (f2sum(acc1[2]) + b0.z) * sc;
        o.w = (f2sum(acc1[3]) + b0.w) * sc;
        *reinterpret_cast<float4*>(&so[(lane + 32) * SO_STRIDE + colw]) = o;
        o.x = (f2sum(acc1[4]) + b1.x) * sc;
        o.y = (f2sum(acc1[5]) + b1.y) * sc;
        o.z = (f2sum(acc1[6]) + b1.z) * sc;
        o.w = (f2sum(acc1[7]) + b1.w) * sc;
        *reinterpret_cast<float4*>(&so[(lane + 32) * SO_STRIDE + colw + 4]) = o;
    }
    __syncthreads();

    float* dst = (ct == 0) ? g_q : (ct == 1) ? g_k : g_v;
    for (int idx = t; idx < 64 * 24; idx += 384) {
        int r = idx / 24, c4 = idx % 24;
        if (row0 + r < N)
            *reinterpret_cast<float4*>(&dst[(row0 + r) * DIM + 4 * c4]) =
                *reinterpret_cast<const float4*>(&so[r * SO_STRIDE + 4 * c4]);
    }
}

// ---------------- kernel 4: attention, warp/query, float4 lanes ----------
__global__ __launch_bounds__(256) void k_attn(const int* __restrict__ index_1, int N) {
    int warp = threadIdx.x >> 5;
    int lane = threadIdx.x & 31;
    int i = blockIdx.x * 8 + warp;
    if (i >= N) return;

    int dim0 = (lane < 24) ? 4 * lane : 0;

    float4 q4 = *reinterpret_cast<const float4*>(&g_q[i * DIM + dim0]);
    int qi = g_quant[i];

    int idx = 0, qn = 0;
    if (lane < KNBR) {
        idx = index_1[i * KNBR + lane];
        qn = g_quant[idx];
    }

    float l = 0.f;
    float4 o4 = make_float4(0.f, 0.f, 0.f, 0.f);

    #pragma unroll 2
    for (int j = 0; j < KNBR; j++) {
        int nj = __shfl_sync(0xFFFFFFFFu, idx, j);
        int qj = __shfl_sync(0xFFFFFFFFu, qn, j);
        int rr[3];
        rr[0] = ((qi      ) & 255) - ((qj      ) & 255) + NBIAS;
        rr[1] = ((qi >>  8) & 255) - ((qj >>  8) & 255) + NBIAS;
        rr[2] = ((qi >> 16) & 255) - ((qj >> 16) & 255) + NBIAS;

        float4 k4 = *reinterpret_cast<const float4*>(&g_k[nj * DIM + dim0]);
        float4 v4 = *reinterpret_cast<const float4*>(&g_v[nj * DIM + dim0]);

        float a = q4.x * k4.x;
        a = fmaf(q4.y, k4.y, a);
        a = fmaf(q4.z, k4.z, a);
        a = fmaf(q4.w, k4.w, a);

        #pragma unroll
        for (int c = 0; c < 3; c++) {
            const uint4* tp = reinterpret_cast<const uint4*>(
                &g_tqk[(c * TBL_ROWS + rr[c]) * 192]) + lane;
            uint4 u = *tp;
            float2 tq01 = bf2f(u.x);
            float2 tq23 = bf2f(u.y);
            float2 tk01 = bf2f(u.z);
            float2 tk23 = bf2f(u.w);
            a = fmaf(q4.x, tq01.x, a);
            a = fmaf(q4.y, tq01.y, a);
            a = fmaf(q4.z, tq23.x, a);
            a = fmaf(q4.w, tq23.y, a);
            a = fmaf(k4.x, tk01.x, a);
            a = fmaf(k4.y, tk01.y, a);
            a = fmaf(k4.z, tk23.x, a);
            a = fmaf(k4.w, tk23.y, a);

            float4 tv4 = *reinterpret_cast<const float4*>(
                &g_tv[(c * TBL_ROWS + rr[c]) * DIM + dim0]);
            v4.x += tv4.x; v4.y += tv4.y; v4.z += tv4.z; v4.w += tv4.w;
        }

        a += __shfl_xor_sync(0xFFFFFFFFu, a, 1);
        a += __shfl_xor_sync(0xFFFFFFFFu, a, 2);

        float w = __expf(a);
        l += w;
        o4.x = fmaf(w, v4.x, o4.x);
        o4.y = fmaf(w, v4.y, o4.y);
        o4.z = fmaf(w, v4.z, o4.z);
        o4.w = fmaf(w, v4.w, o4.w);
    }

    if (lane < 24) {
        float rl = __frcp_rn(l);
        float4 x;
        x.x = o4.x * rl; x.y = o4.y * rl; x.z = o4.z * rl; x.w = o4.w * rl;
        *reinterpret_cast<float4*>(&g_x[i * DIM + dim0]) = x;
    }
}

// ---------------- kernel 5: proj GEMM, rows-on-lanes, uniform weights ----
__global__ __launch_bounds__(384, 2) void k_proj(const float* __restrict__ b,
                                                 float* __restrict__ out, int N) {
    __shared__ __align__(16) float sf[64 * SF_STRIDE];
    __shared__ __align__(16) float so[64 * SO_STRIDE];
    int row0 = blockIdx.x * 64;
    int t = threadIdx.x;

    for (int idx = t; idx < 64 * 24; idx += 384) {
        int r = idx / 24, c4 = idx % 24;
        float4 v = (row0 + r < N)
            ? *reinterpret_cast<const float4*>(&g_x[(row0 + r) * DIM + 4 * c4])
            : make_float4(0.f, 0.f, 0.f, 0.f);
        *reinterpret_cast<float2*>(&sf[r * SF_STRIDE + 4 * c4])     = make_float2(v.x, v.y);
        *reinterpret_cast<float2*>(&sf[r * SF_STRIDE + 4 * c4 + 2]) = make_float2(v.z, v.w);
    }
    __syncthreads();

    int wid = t >> 5, lane = t & 31;
    int colw = wid * 8;

    ull acc0[8], acc1[8];
    #pragma unroll
    for (int c = 0; c < 8; c++) { acc0[c] = 0ull; acc1[c] = 0ull; }

    const ull* wbase = reinterpret_cast<const ull*>(g_wp) + colw;
    const float* s0p = &sf[lane * SF_STRIDE];
    const float* s1p = &sf[(lane + 32) * SF_STRIDE];

    #pragma unroll 4
    for (int dp = 0; dp < 48; dp++) {
        ulonglong2 wa = *reinterpret_cast<const ulonglong2*>(wbase + dp * 96);
        ulonglong2 wb = *reinterpret_cast<const ulonglong2*>(wbase + dp * 96 + 2);
        ulonglong2 wc = *reinterpret_cast<const ulonglong2*>(wbase + dp * 96 + 4);
        ulonglong2 wd = *reinterpret_cast<const ulonglong2*>(wbase + dp * 96 + 6);
        ull s0 = *reinterpret_cast<const ull*>(s0p + 2 * dp);
        ull s1 = *reinterpret_cast<const ull*>(s1p + 2 * dp);
        acc0[0] = fma2(s0, wa.x, acc0[0]);  acc1[0] = fma2(s1, wa.x, acc1[0]);
        acc0[1] = fma2(s0, wa.y, acc0[1]);  acc1[1] = fma2(s1, wa.y, acc1[1]);
        acc0[2] = fma2(s0, wb.x, acc0[2]);  acc1[2] = fma2(s1, wb.x, acc1[2]);
        acc0[3] = fma2(s0, wb.y, acc0[3]);  acc1[3] = fma2(s1, wb.y, acc1[3]);
        acc0[4] = fma2(s0, wc.x, acc0[4]);  acc1[4] = fma2(s1, wc.x, acc1[4]);
        acc0[5] = fma2(s0, wc.y, acc0[5]);  acc1[5] = fma2(s1, wc.y, acc1[5]);
        acc0[6] = fma2(s0, wd.x, acc0[6]);  acc1[6] = fma2(s1, wd.x, acc1[6]);
        acc0[7] = fma2(s0, wd.y, acc0[7]);  acc1[7] = fma2(s1, wd.y, acc1[7]);
    }

    float4 b0 = *reinterpret_cast<const float4*>(&b[colw]);
    float4 b1 = *reinterpret_cast<const float4*>(&b[colw + 4]);
    {
        float4 o;
        o.x = f2sum(acc0[0]) + b0.x;
        o.y = f2sum(acc0[1]) + b0.y;
        o.z = f2sum(acc0[2]) + b0.z;
        o.w = f2sum(acc0[3]) + b0.w;
        *reinterpret_cast<float4*>(&so[lane * SO_STRIDE + colw]) = o;
        o.x = f2sum(acc0[4]) + b1.x;
        o.y = f2sum(acc0[5]) + b1.y;
        o.z = f2sum(acc0[6]) + b1.z;
        o.w = f2sum(acc0[7]) + b1.w;
        *reinterpret_cast<float4*>(&so[lane * SO_STRIDE + colw + 4]) = o;
        o.x = f2sum(acc1[0]) + b0.x;
        o.y = f2sum(acc1[1]) + b0.y;
        o.z = f2sum(acc1[2]) + b0.z;
        o.w = f2sum(acc1[3]) + b0.w;
        *reinterpret_cast<float4*>(&so[(lane + 32) * SO_STRIDE + colw]) = o;
        o.x = f2sum(acc1[4]) + b1.x;
        o.y = f2sum(acc1[5]) + b1.y;
        o.z = f2sum(acc1[6]) + b1.z;
        o.w = f2sum(acc1[7]) + b1.w;
        *reinterpret_cast<float4*>(&so[(lane + 32) * SO_STRIDE + colw + 4]) = o;
    }
    __syncthreads();

    for (int idx = t; idx < 64 * 24; idx += 384) {
        int r = idx / 24, c4 = idx % 24;
        if (row0 + r < N)
            *reinterpret_cast<float4*>(&out[(row0 + r) * DIM + 4 * c4]) =
                *reinterpret_cast<const float4*>(&so[r * SO_STRIDE + 4 * c4]);
    }
}

// ---------------- launch ----------------
extern "C" void kernel_launch(void* const* d_in, const int* in_sizes, int n_in,
                              void* d_out, int out_size) {
    int p = 0;
    const float* feats = (const float*)d_in[p++];
    const float* xyz   = (const float*)d_in[p++];
    p++;                                                // index_0
    int N = in_sizes[p] - 1; p++;                       // index_0_offsets
    if (p < n_in && in_sizes[p] == 1) p++;              // n_max
    const int* index_1 = (const int*)d_in[p++];
    const float* shift = nullptr;
    if (p < n_in && in_sizes[p] == 1) { shift = (const float*)d_in[p]; p++; }
    const float* W_qkv  = (const float*)d_in[p++];
    const float* b_qkv  = (const float*)d_in[p++];
    const float* tq     = (const float*)d_in[p++];
    const float* tk     = (const float*)d_in[p++];
    const float* tv     = (const float*)d_in[p++];
    const float* W_proj = (const float*)d_in[p++];
    const float* b_proj = (const float*)d_in[p++];
    float* out = (float*)d_out;

    if (N > MAXN) N = MAXN;

    int nrb = (N + 63) / 64;
    k_init_min<<<1, 32>>>();
    k_min<<<128, 256>>>(xyz, N);
    k_prep<<<(N + 255) / 256, 256>>>(xyz, shift, tq, tk, tv, W_qkv, W_proj, N);
    k_qkv<<<dim3(nrb, 3), 384>>>(feats, b_qkv, N);
    k_attn<<<(N + 7) / 8, 256>>>(index_1, N);
    k_proj<<<nrb, 384>>>(b_proj, out, N);
}

// round 8
// speedup vs baseline: 1.4719x; 1.4719x over previous
#include <cuda_runtime.h>
#include <cuda_bf16.h>
#include <math.h>
#include <stdint.h>

// ---------------- problem constants ----------------
#define MAXN   50000
#define DIM    96
#define KNBR   16
#define NBIAS  15
#define SCALE  0.25f
#define TBL_ROWS 64
#define APAD   104          // padded row stride (bf16 elems) for smem tiles

// ---------------- device scratch ----------------
__device__ __align__(16) float g_q[MAXN * DIM];
__device__ __align__(16) float g_k[MAXN * DIM];
__device__ __align__(16) float g_v[MAXN * DIM];
__device__ __align__(16) float g_x[MAXN * DIM];
// tq/tk interleaved bf16: [c][row][24 groups][tq0..3, tk0..3]
__device__ __align__(16) __nv_bfloat16 g_tqk[3 * TBL_ROWS * 192];
// tv fp32 c-major: [c][row][96]
__device__ __align__(16) float g_tv[3 * TBL_ROWS * DIM];
// W images (bf16 hi/lo), layout [tile][k=96][n pad 104]
__device__ __align__(16) __nv_bfloat16 g_wqh[3 * 96 * APAD];
__device__ __align__(16) __nv_bfloat16 g_wql[3 * 96 * APAD];
__device__ __align__(16) __nv_bfloat16 g_wph[96 * APAD];
__device__ __align__(16) __nv_bfloat16 g_wpl[96 * APAD];
__device__ int g_quant[MAXN];
__device__ unsigned int g_minbits[3];

// ---------------- helpers ----------------
__device__ __forceinline__ float2 bf2f(unsigned u) {
    __nv_bfloat162 h = *reinterpret_cast<__nv_bfloat162*>(&u);
    return __bfloat1622float2(h);
}
__device__ __forceinline__ uint32_t smem_u32(const void* p) {
    uint32_t a;
    asm("{ .reg .u64 t; cvta.to.shared.u64 t, %1; cvt.u32.u64 %0, t; }"
        : "=r"(a) : "l"(p));
    return a;
}
__device__ __forceinline__ void ldsm_x4(uint32_t* r, uint32_t addr) {
    asm volatile("ldmatrix.sync.aligned.m8n8.x4.shared.b16 {%0,%1,%2,%3}, [%4];"
        : "=r"(r[0]), "=r"(r[1]), "=r"(r[2]), "=r"(r[3]) : "r"(addr));
}
__device__ __forceinline__ void ldsm_x2t(uint32_t& r0, uint32_t& r1, uint32_t addr) {
    asm volatile("ldmatrix.sync.aligned.m8n8.x2.trans.shared.b16 {%0,%1}, [%2];"
        : "=r"(r0), "=r"(r1) : "r"(addr));
}
__device__ __forceinline__ void mma16816(float* d, const uint32_t* a,
                                         uint32_t b0, uint32_t b1) {
    asm volatile(
        "mma.sync.aligned.m16n8k16.row.col.f32.bf16.bf16.f32 "
        "{%0,%1,%2,%3}, {%4,%5,%6,%7}, {%8,%9}, {%0,%1,%2,%3};"
        : "+f"(d[0]), "+f"(d[1]), "+f"(d[2]), "+f"(d[3])
        : "r"(a[0]), "r"(a[1]), "r"(a[2]), "r"(a[3]), "r"(b0), "r"(b1));
}

// ---------------- kernel 0: init min ----------------
__global__ void k_init_min() {
    if (threadIdx.x < 3) g_minbits[threadIdx.x] = 0x7F800000u;
}

// ---------------- kernel 1: xyz min ----------------
__global__ void k_min(const float* __restrict__ xyz, int N) {
    float v0 = INFINITY, v1 = INFINITY, v2 = INFINITY;
    for (int i = blockIdx.x * blockDim.x + threadIdx.x; i < N;
         i += gridDim.x * blockDim.x) {
        v0 = fminf(v0, xyz[i * 3 + 0]);
        v1 = fminf(v1, xyz[i * 3 + 1]);
        v2 = fminf(v2, xyz[i * 3 + 2]);
    }
    #pragma unroll
    for (int m = 16; m >= 1; m >>= 1) {
        v0 = fminf(v0, __shfl_xor_sync(0xFFFFFFFFu, v0, m));
        v1 = fminf(v1, __shfl_xor_sync(0xFFFFFFFFu, v1, m));
        v2 = fminf(v2, __shfl_xor_sync(0xFFFFFFFFu, v2, m));
    }
    if ((threadIdx.x & 31) == 0) {
        atomicMin(&g_minbits[0], __float_as_uint(v0));
        atomicMin(&g_minbits[1], __float_as_uint(v1));
        atomicMin(&g_minbits[2], __float_as_uint(v2));
    }
}

// ---------------- kernel 2: quant + table repack + W images ----------------
__global__ void k_prep(const float* __restrict__ xyz,
                       const float* __restrict__ shift_ptr,
                       const float* __restrict__ tq,
                       const float* __restrict__ tk,
                       const float* __restrict__ tv,
                       const float* __restrict__ Wq,
                       const float* __restrict__ Wp, int N) {
    int i = blockIdx.x * blockDim.x + threadIdx.x;
    if (i < N) {
        float shift = shift_ptr ? *shift_ptr : 0.0f;
        int packed = 0;
        #pragma unroll
        for (int c = 0; c < 3; c++) {
            float mn = __uint_as_float(g_minbits[c]);
            float m = fmodf(xyz[i * 3 + c] - mn + shift, 4.0f);
            if (m < 0.0f) m += 4.0f;
            int q = (int)floorf(m * 4.0f);
            q = max(0, min(15, q));
            packed |= q << (8 * c);
        }
        g_quant[i] = packed;
    }
    if (i < 3 * TBL_ROWS * DIM) {
        int c = i / (TBL_ROWS * DIM);
        int rem = i % (TBL_ROWS * DIM);
        int r = rem / DIM, dim = rem % DIM;
        int src = (r * DIM + dim) * 3 + c;
        int gdst = (c * TBL_ROWS + r) * 192 + (dim / 4) * 8 + (dim % 4);
        g_tqk[gdst]     = __float2bfloat16(tq[src]);
        g_tqk[gdst + 4] = __float2bfloat16(tk[src]);
        g_tv[(c * TBL_ROWS + r) * DIM + dim] = tv[src];
    }
    // W_qkv image: [tile][k][n%96] bf16 hi/lo
    if (i < 96 * 288) {
        int k = i / 288, n = i % 288;
        float x = Wq[k * 288 + n];
        __nv_bfloat16 hi = __float2bfloat16(x);
        __nv_bfloat16 lo = __float2bfloat16(x - __bfloat162float(hi));
        int dst = (n / 96) * 96 * APAD + k * APAD + (n % 96);
        g_wqh[dst] = hi;
        g_wql[dst] = lo;
    }
    // W_proj image
    if (i < 96 * 96) {
        int k = i / 96, n = i % 96;
        float x = Wp[k * 96 + n];
        __nv_bfloat16 hi = __float2bfloat16(x);
        __nv_bfloat16 lo = __float2bfloat16(x - __bfloat162float(hi));
        g_wph[k * APAD + n] = hi;
        g_wpl[k * APAD + n] = lo;
    }
}

// ---------------- tensor-core GEMM: 128 rows/CTA x 96 cols/tile ----------
// 256 thr = 8 warps; warp w owns rows w*16..w*16+15, all 96 cols.
// bf16 hi/lo 3-pass (AhBh + AhBl + AlBh) accumulated in fp32.
// QKV: gridDim.y = 3 selects q/k/v tile; else proj.
template<bool QKV>
__global__ __launch_bounds__(256) void k_gemm(const float* __restrict__ src,
                                              const float* __restrict__ bias,
                                              float* __restrict__ outp, int N) {
    extern __shared__ __align__(16) char smem[];
    __nv_bfloat16* Ah = reinterpret_cast<__nv_bfloat16*>(smem);   // 128*APAD
    __nv_bfloat16* Al = Ah + 128 * APAD;
    __nv_bfloat16* Bh = Al + 128 * APAD;                           // 96*APAD
    __nv_bfloat16* Bl = Bh + 96 * APAD;

    int t = threadIdx.x;
    int row0 = blockIdx.x * 128;
    int tile = QKV ? blockIdx.y : 0;

    // copy W tile images (hi/lo)
    {
        const uint4* wh4 = reinterpret_cast<const uint4*>(
            (QKV ? g_wqh : g_wph) + tile * 96 * APAD);
        const uint4* wl4 = reinterpret_cast<const uint4*>(
            (QKV ? g_wql : g_wpl) + tile * 96 * APAD);
        for (int i = t; i < 96 * APAD / 8; i += 256) {
            reinterpret_cast<uint4*>(Bh)[i] = wh4[i];
            reinterpret_cast<uint4*>(Bl)[i] = wl4[i];
        }
    }

    // A convert: fp32 -> bf16 hi/lo (pairs of k for 4B stores)
    const float* sp = QKV ? src : g_x;
    for (int i = t; i < 128 * 48; i += 256) {
        int r = i / 48, kp = (i % 48) * 2;
        float x0 = 0.f, x1 = 0.f;
        if (row0 + r < N) {
            float2 v = *reinterpret_cast<const float2*>(&sp[(row0 + r) * 96 + kp]);
            x0 = v.x; x1 = v.y;
        }
        __nv_bfloat16 h0 = __float2bfloat16(x0);
        __nv_bfloat16 h1 = __float2bfloat16(x1);
        __nv_bfloat16 l0 = __float2bfloat16(x0 - __bfloat162float(h0));
        __nv_bfloat16 l1 = __float2bfloat16(x1 - __bfloat162float(h1));
        *reinterpret_cast<__nv_bfloat162*>(&Ah[r * APAD + kp]) =
            __nv_bfloat162(h0, h1);
        *reinterpret_cast<__nv_bfloat162*>(&Al[r * APAD + kp]) =
            __nv_bfloat162(l0, l1);
    }
    __syncthreads();

    int wid = t >> 5, lane = t & 31;
    int wrow = wid * 16;

    // A fragments: 6 k-steps, hi+lo
    uint32_t ah[6][4], al[6][4];
    {
        int arow = wrow + (lane & 15);
        int akh = (lane >> 4) * 8;
        uint32_t aAh = smem_u32(Ah), aAl = smem_u32(Al);
        #pragma unroll
        for (int ks = 0; ks < 6; ks++) {
            uint32_t off = (uint32_t)(arow * APAD + ks * 16 + akh) * 2;
            ldsm_x4(ah[ks], aAh + off);
            ldsm_x4(al[ks], aAl + off);
        }
    }

    uint32_t aBh = smem_u32(Bh), aBl = smem_u32(Bl);
    int bkl = lane & 15;
    float scl = (QKV && tile == 0) ? SCALE : 1.0f;
    const float* bs = bias + (QKV ? tile * 96 : 0);
    float* dst;
    if (QKV) dst = (tile == 0) ? g_q : (tile == 1) ? g_k : g_v;
    else     dst = outp;

    int erow = wrow + (lane >> 2);
    int ecol = 2 * (lane & 3);
    bool ok1 = (row0 + erow) < N;
    bool ok2 = (row0 + erow + 8) < N;

    #pragma unroll
    for (int nt = 0; nt < 12; nt++) {
        float d[4] = {0.f, 0.f, 0.f, 0.f};
        #pragma unroll
        for (int ks = 0; ks < 6; ks++) {
            uint32_t boff = (uint32_t)((ks * 16 + bkl) * APAD + nt * 8) * 2;
            uint32_t bh0, bh1, bl0, bl1;
            ldsm_x2t(bh0, bh1, aBh + boff);
            ldsm_x2t(bl0, bl1, aBl + boff);
            mma16816(d, ah[ks], bh0, bh1);
            mma16816(d, ah[ks], bl0, bl1);
            mma16816(d, al[ks], bh0, bh1);
        }
        float2 bv = *reinterpret_cast<const float2*>(&bs[nt * 8 + ecol]);
        float2 o0, o1;
        o0.x = (d[0] + bv.x) * scl;
        o0.y = (d[1] + bv.y) * scl;
        o1.x = (d[2] + bv.x) * scl;
        o1.y = (d[3] + bv.y) * scl;
        if (ok1)
            *reinterpret_cast<float2*>(&dst[(row0 + erow) * 96 + nt * 8 + ecol]) = o0;
        if (ok2)
            *reinterpret_cast<float2*>(&dst[(row0 + erow + 8) * 96 + nt * 8 + ecol]) = o1;
    }
}

// ---------------- kernel: attention, warp/query, float4 lanes ----------
__global__ __launch_bounds__(256) void k_attn(const int* __restrict__ index_1, int N) {
    int warp = threadIdx.x >> 5;
    int lane = threadIdx.x & 31;
    int i = blockIdx.x * 8 + warp;
    if (i >= N) return;

    int dim0 = (lane < 24) ? 4 * lane : 0;

    float4 q4 = *reinterpret_cast<const float4*>(&g_q[i * DIM + dim0]);
    int qi = g_quant[i];

    int idx = 0, qn = 0;
    if (lane < KNBR) {
        idx = index_1[i * KNBR + lane];
        qn = g_quant[idx];
    }

    float l = 0.f;
    float4 o4 = make_float4(0.f, 0.f, 0.f, 0.f);

    #pragma unroll 2
    for (int j = 0; j < KNBR; j++) {
        int nj = __shfl_sync(0xFFFFFFFFu, idx, j);
        int qj = __shfl_sync(0xFFFFFFFFu, qn, j);
        int rr[3];
        rr[0] = ((qi      ) & 255) - ((qj      ) & 255) + NBIAS;
        rr[1] = ((qi >>  8) & 255) - ((qj >>  8) & 255) + NBIAS;
        rr[2] = ((qi >> 16) & 255) - ((qj >> 16) & 255) + NBIAS;

        float4 k4 = *reinterpret_cast<const float4*>(&g_k[nj * DIM + dim0]);
        float4 v4 = *reinterpret_cast<const float4*>(&g_v[nj * DIM + dim0]);

        float a = q4.x * k4.x;
        a = fmaf(q4.y, k4.y, a);
        a = fmaf(q4.z, k4.z, a);
        a = fmaf(q4.w, k4.w, a);

        #pragma unroll
        for (int c = 0; c < 3; c++) {
            const uint4* tp = reinterpret_cast<const uint4*>(
                &g_tqk[(c * TBL_ROWS + rr[c]) * 192]) + lane;
            uint4 u = *tp;
            float2 tq01 = bf2f(u.x);
            float2 tq23 = bf2f(u.y);
            float2 tk01 = bf2f(u.z);
            float2 tk23 = bf2f(u.w);
            a = fmaf(q4.x, tq01.x, a);
            a = fmaf(q4.y, tq01.y, a);
            a = fmaf(q4.z, tq23.x, a);
            a = fmaf(q4.w, tq23.y, a);
            a = fmaf(k4.x, tk01.x, a);
            a = fmaf(k4.y, tk01.y, a);
            a = fmaf(k4.z, tk23.x, a);
            a = fmaf(k4.w, tk23.y, a);

            float4 tv4 = *reinterpret_cast<const float4*>(
                &g_tv[(c * TBL_ROWS + rr[c]) * DIM + dim0]);
            v4.x += tv4.x; v4.y += tv4.y; v4.z += tv4.z; v4.w += tv4.w;
        }

        a += __shfl_xor_sync(0xFFFFFFFFu, a, 1);
        a += __shfl_xor_sync(0xFFFFFFFFu, a, 2);

        float w = __expf(a);
        l += w;
        o4.x = fmaf(w, v4.x, o4.x);
        o4.y = fmaf(w, v4.y, o4.y);
        o4.z = fmaf(w, v4.z, o4.z);
        o4.w = fmaf(w, v4.w, o4.w);
    }

    if (lane < 24) {
        float rl = __frcp_rn(l);
        float4 x;
        x.x = o4.x * rl; x.y = o4.y * rl; x.z = o4.z * rl; x.w = o4.w * rl;
        *reinterpret_cast<float4*>(&g_x[i * DIM + dim0]) = x;
    }
}

// ---------------- launch ----------------
extern "C" void kernel_launch(void* const* d_in, const int* in_sizes, int n_in,
                              void* d_out, int out_size) {
    int p = 0;
    const float* feats = (const float*)d_in[p++];
    const float* xyz   = (const float*)d_in[p++];
    p++;                                                // index_0
    int N = in_sizes[p] - 1; p++;                       // index_0_offsets
    if (p < n_in && in_sizes[p] == 1) p++;              // n_max
    const int* index_1 = (const int*)d_in[p++];
    const float* shift = nullptr;
    if (p < n_in && in_sizes[p] == 1) { shift = (const float*)d_in[p]; p++; }
    const float* W_qkv  = (const float*)d_in[p++];
    const float* b_qkv  = (const float*)d_in[p++];
    const float* tq     = (const float*)d_in[p++];
    const float* tk     = (const float*)d_in[p++];
    const float* tv     = (const float*)d_in[p++];
    const float* W_proj = (const float*)d_in[p++];
    const float* b_proj = (const float*)d_in[p++];
    float* out = (float*)d_out;

    if (N > MAXN) N = MAXN;

    // smem: A hi/lo (128*APAD each) + B hi/lo (96*APAD each), bf16
    const int SMEM = (128 * APAD * 2 + 96 * APAD * 2) * 2;   // 93184 B
    static bool attr_set = false;
    if (!attr_set) {
        cudaFuncSetAttribute(k_gemm<true>,
                             cudaFuncAttributeMaxDynamicSharedMemorySize, SMEM);
        cudaFuncSetAttribute(k_gemm<false>,
                             cudaFuncAttributeMaxDynamicSharedMemorySize, SMEM);
        attr_set = true;
    }

    int ngb = (N + 127) / 128;
    k_init_min<<<1, 32>>>();
    k_min<<<128, 256>>>(xyz, N);
    k_prep<<<(N + 255) / 256, 256>>>(xyz, shift, tq, tk, tv, W_qkv, W_proj, N);
    k_gemm<true><<<dim3(ngb, 3), 256, SMEM>>>(feats, b_qkv, nullptr, N);
    k_attn<<<(N + 7) / 8, 256>>>(index_1, N);
    k_gemm<false><<<ngb, 256, SMEM>>>(nullptr, b_proj, out, N);
}